// round 2
// baseline (speedup 1.0000x reference)
#include <cuda_runtime.h>
#include <math.h>

// Problem constants (fixed by the dataset)
#define BB   4
#define CC   32
#define NN   2048
#define PP   12
#define OUTC 32
#define TM   128
#define TN   256       // 8 aggregated feature maps * 32 channels
#define KT   32
#define AS2S 264       // padded row stride (floats) for duplicated A tile
#define EPSV 1e-5f
#define NEG_SLOPE 0.01f

// Scratch (device globals; no runtime allocation)
__device__ float g_xp[(size_t)BB * PP * NN * CC];   // [bp][n][c], 12.6 MB
__device__ float g_deg[NN];
__device__ float g_delta;

// Packed fp32x2 FMA (sm_103a FFMA2) — operands live in 64-bit regs.
__device__ __forceinline__ unsigned long long ffma2(
    unsigned long long a, unsigned long long b, unsigned long long c) {
    unsigned long long d;
    asm("fma.rn.f32x2 %0, %1, %2, %3;" : "=l"(d) : "l"(a), "l"(b), "l"(c));
    return d;
}

// ---------------------------------------------------------------------------
__global__ void deg_kernel(const float* __restrict__ A) {
    int row  = blockIdx.x * (blockDim.x >> 5) + (threadIdx.x >> 5);
    int lane = threadIdx.x & 31;
    const float* r = A + (size_t)row * NN;
    float s = 0.f;
    for (int j = lane; j < NN; j += 32) s += r[j];
    #pragma unroll
    for (int o = 16; o; o >>= 1) s += __shfl_xor_sync(0xffffffffu, s, o);
    if (lane == 0) g_deg[row] = s;
}

__global__ void delta_kernel() {
    __shared__ float red[32];
    int tid = threadIdx.x;
    float s = 0.f;
    for (int i = tid; i < NN; i += blockDim.x) s += logf(g_deg[i] + 1.f);
    #pragma unroll
    for (int o = 16; o; o >>= 1) s += __shfl_xor_sync(0xffffffffu, s, o);
    if ((tid & 31) == 0) red[tid >> 5] = s;
    __syncthreads();
    if (tid < 32) {
        float v = (tid < (int)(blockDim.x >> 5)) ? red[tid] : 0.f;
        #pragma unroll
        for (int o = 16; o; o >>= 1) v += __shfl_xor_sync(0xffffffffu, v, o);
        if (tid == 0) g_delta = v / (float)NN;
    }
}

__global__ void transpose_kernel(const float* __restrict__ X) {
    int idx = blockIdx.x * blockDim.x + threadIdx.x;
    if (idx >= BB * PP * NN * CC) return;
    int ch = idx & (CC - 1);
    int j  = (idx >> 5) & (NN - 1);
    int bp = idx >> 16;
    int b = bp / PP, p = bp % PP;
    g_xp[idx] = X[(((size_t)b * CC + ch) * NN + j) * PP + p];
}

// ---------------------------------------------------------------------------
// Fused main kernel (FFMA2 mainloop):
//   ACC[128][256] = A_tile @ F, F = 8 on-the-fly features x 32 channels,
//   then aggregator epilogue + scaler-folded Theta projection.
// ---------------------------------------------------------------------------
__global__ __launch_bounds__(512, 1)
void pna_kernel(const float* __restrict__ A, const float* __restrict__ Theta,
                const float* __restrict__ Bias, float* __restrict__ out) {
    extern __shared__ float sm[];
    const int bp = blockIdx.y;
    const int i0 = blockIdx.x * TM;
    const int b  = bp / PP, p = bp % PP;
    const float* __restrict__ xp = g_xp + (size_t)bp * NN * CC;

    float* As2 = sm;                    // [KT][AS2S]  duplicated A: {a,a} pairs
    float* Fs  = sm + KT * AS2S;        // [KT][TN]

    const int tid = threadIdx.x;
    const int ty = tid >> 5;            // 0..15
    const int tx = tid & 31;            // 0..31

    unsigned long long acc[8][4];       // 8 rows x 4 col-pairs
    #pragma unroll
    for (int r = 0; r < 8; r++)
        #pragma unroll
        for (int c2 = 0; c2 < 4; c2++) acc[r][c2] = 0ull;

    const int ati = tid >> 2;           // 0..127  dest row within tile
    const int akk = (tid & 3) << 3;     // 0,8,16,24
    const int fkk = tid >> 5;           // kk for F staging (it=0)
    const int fch = tid & 31;

    // prefetch registers
    float4 pa0, pa1;
    float  px0, px1;
    {
        const float4* src = reinterpret_cast<const float4*>(
            A + (size_t)(i0 + ati) * NN + akk);
        pa0 = src[0]; pa1 = src[1];
        px0 = xp[(size_t)fkk * CC + fch];
        px1 = xp[(size_t)(16 + fkk) * CC + fch];
    }

    for (int k0 = 0; k0 < NN; k0 += KT) {
        // ---- stage duplicated A tile ----
        {
            float* d0 = As2 + akk * AS2S + 2 * ati;
            *reinterpret_cast<float2*>(d0 + 0 * AS2S) = make_float2(pa0.x, pa0.x);
            *reinterpret_cast<float2*>(d0 + 1 * AS2S) = make_float2(pa0.y, pa0.y);
            *reinterpret_cast<float2*>(d0 + 2 * AS2S) = make_float2(pa0.z, pa0.z);
            *reinterpret_cast<float2*>(d0 + 3 * AS2S) = make_float2(pa0.w, pa0.w);
            *reinterpret_cast<float2*>(d0 + 4 * AS2S) = make_float2(pa1.x, pa1.x);
            *reinterpret_cast<float2*>(d0 + 5 * AS2S) = make_float2(pa1.y, pa1.y);
            *reinterpret_cast<float2*>(d0 + 6 * AS2S) = make_float2(pa1.z, pa1.z);
            *reinterpret_cast<float2*>(d0 + 7 * AS2S) = make_float2(pa1.w, pa1.w);
        }
        // ---- stage F tile from prefetched x ----
        #pragma unroll
        for (int it = 0; it < 2; it++) {
            float x = it ? px1 : px0;
            int kk = fkk + it * 16;
            float x2 = x * x;
            float ep = expf(x);
            float en = expf(-x);
            float* f = Fs + kk * TN + fch;
            f[0]   = x;
            f[32]  = x2;
            f[64]  = x2 * x;
            f[96]  = x2 * x2;
            f[128] = x * ep;
            f[160] = ep;
            f[192] = x * en;
            f[224] = en;
        }
        __syncthreads();

        // ---- prefetch next tile (hidden behind kk loop) ----
        if (k0 + KT < NN) {
            const float4* src = reinterpret_cast<const float4*>(
                A + (size_t)(i0 + ati) * NN + (k0 + KT) + akk);
            pa0 = src[0]; pa1 = src[1];
            px0 = xp[(size_t)(k0 + KT + fkk) * CC + fch];
            px1 = xp[(size_t)(k0 + KT + 16 + fkk) * CC + fch];
        }

        // ---- 128x256x32 FFMA2 tile ----
        #pragma unroll 2
        for (int kk = 0; kk < KT; kk++) {
            const ulonglong2* ap = reinterpret_cast<const ulonglong2*>(
                As2 + kk * AS2S + ty * 16);
            const ulonglong2* bpntr = reinterpret_cast<const ulonglong2*>(
                Fs + kk * TN + tx * 8);
            ulonglong2 a01 = ap[0], a23 = ap[1], a45 = ap[2], a67 = ap[3];
            ulonglong2 b01 = bpntr[0], b23 = bpntr[1];
            unsigned long long av[8] = {a01.x, a01.y, a23.x, a23.y,
                                        a45.x, a45.y, a67.x, a67.y};
            unsigned long long bv[4] = {b01.x, b01.y, b23.x, b23.y};
            #pragma unroll
            for (int r = 0; r < 8; r++)
                #pragma unroll
                for (int c2 = 0; c2 < 4; c2++)
                    acc[r][c2] = ffma2(av[r], bv[c2], acc[r][c2]);
        }
        __syncthreads();
    }

    // ---- spill accumulators to smem: ACC[128][256] (overwrites As2/Fs) ----
    float* ACC = sm;
    #pragma unroll
    for (int r = 0; r < 8; r++) {
        ulonglong2* d = reinterpret_cast<ulonglong2*>(&ACC[(ty * 8 + r) * TN + tx * 8]);
        d[0] = make_ulonglong2(acc[r][0], acc[r][1]);
        d[1] = make_ulonglong2(acc[r][2], acc[r][3]);
    }
    __syncthreads();

    // ---- phase A: aggregator math, in place ----
    for (int e = tid; e < TM * CC; e += 512) {
        int i  = e >> 5;
        int ch = e & 31;
        float* row = &ACC[i * TN];
        float S1  = row[ch],       S2  = row[32 + ch];
        float S3  = row[64 + ch],  S4  = row[96 + ch];
        float SXP = row[128 + ch], SEP = row[160 + ch];
        float SXN = row[192 + ch], SEN = row[224 + ch];

        float x    = xp[(size_t)(i0 + i) * CC + ch];
        float dg   = g_deg[i0 + i];
        float dinv = 1.f / fmaxf(dg, EPSV);
        float m1 = S1 * dinv, m2 = S2 * dinv, m3 = S3 * dinv, m4 = S4 * dinv;
        float smax = SXP / (SEP + EPSV);
        float smin = SXN / (SEN + EPSV);
        float var  = fmaxf(m2 - m1 * m1, 0.f);
        float stdv = sqrtf(var + EPSV);
        float x2 = x * x, x3 = x2 * x, x4 = x2 * x2;
        float dist = x2 - 2.f * x * m1 + m2;
        float ed2  = x4 - 4.f * x3 * m1 + 6.f * x2 * m2 - 4.f * x * m3 + m4;
        float dstd = sqrtf(fmaxf(ed2 - dist * dist, 0.f) + EPSV);

        row[ch]        = smin;
        row[32  + ch]  = smax;
        row[64  + ch]  = m1;
        row[96  + ch]  = stdv;
        row[128 + ch]  = var;
        row[160 + ch]  = dist;
        row[192 + ch]  = dstd;
    }
    __syncthreads();

    // ---- phase B: scaler-folded Theta projection (f outer, 8 rows inner) ----
    const float delta = g_delta;
    const int o = tx;
    float s8[8], inv8[8], accO[8];
    #pragma unroll
    for (int r = 0; r < 8; r++) {
        int i = ty * 8 + r;
        float dg = g_deg[i0 + i];
        s8[r]   = logf(dg + 1.f) / delta;
        inv8[r] = 1.f / fmaxf(s8[r], EPSV);
        accO[r] = Bias[o];
    }
    #pragma unroll 4
    for (int f = 0; f < 224; f++) {
        float t0 = Theta[f * OUTC + o];
        float t1 = Theta[(224 + f) * OUTC + o];
        float t2 = Theta[(448 + f) * OUTC + o];
        #pragma unroll
        for (int r = 0; r < 8; r++) {
            float fv = ACC[(ty * 8 + r) * TN + f];
            float t  = fmaf(s8[r], t1, fmaf(inv8[r], t2, t0));
            accO[r]  = fmaf(fv, t, accO[r]);
        }
    }
    #pragma unroll
    for (int r = 0; r < 8; r++) {
        int i = ty * 8 + r;
        float v = accO[r];
        v = v > 0.f ? v : NEG_SLOPE * v;
        out[(((size_t)b * OUTC + o) * NN + (i0 + i)) * PP + p] = v;
    }
}

// ---------------------------------------------------------------------------
extern "C" void kernel_launch(void* const* d_in, const int* in_sizes, int n_in,
                              void* d_out, int out_size) {
    const float* X     = (const float*)d_in[0];   // [4,32,2048,12]
    const float* A     = (const float*)d_in[1];   // [2048,2048]
    const float* Theta = (const float*)d_in[2];   // [672,32]
    const float* Bias  = (const float*)d_in[3];   // [32]
    float* out = (float*)d_out;                   // [4,32,2048,12]

    const int smem = TM * TN * (int)sizeof(float);   // 131072 B (>= stage area)
    cudaFuncSetAttribute(pna_kernel, cudaFuncAttributeMaxDynamicSharedMemorySize, smem);

    deg_kernel<<<NN / 8, 256>>>(A);
    delta_kernel<<<1, 1024>>>();
    transpose_kernel<<<(BB * PP * NN * CC + 255) / 256, 256>>>(X);

    dim3 grid(NN / TM, BB * PP);
    pna_kernel<<<grid, 512, smem>>>(A, Theta, Bias, out);
}

// round 4
// speedup vs baseline: 3.6682x; 3.6682x over previous
#include <cuda_runtime.h>
#include <math.h>
#include <stdint.h>

// Problem constants (fixed by the dataset)
#define BB   4
#define CC   32
#define NN   2048
#define PP   12
#define OUTC 32
#define TM   128
#define TN   256        // 8 feature groups * 32 channels
#define KT   32         // K per stage
#define ASS  36         // A smem row stride (36 % 32 == 4 -> conflict-free frags)
#define FSS  264        // F smem row stride (264 % 32 == 8 -> conflict-free frags)
#define ACCS 264        // ACC row stride
#define EPSV 1e-5f
#define NEG_SLOPE 0.01f

#define SMEM_BYTES (TM * ACCS * 4)   // 135168; stage area (As+Fs = 52224) fits inside

// Scratch (device globals; no runtime allocation)
__device__ float g_xp[(size_t)BB * PP * NN * CC];   // [bp][n][c], 12.6 MB
__device__ float g_deg[NN];
__device__ float g_delta;

// ---------------------------------------------------------------------------
__device__ __forceinline__ uint32_t rna_tf32(float x) {
    uint32_t r;
    asm("cvt.rna.tf32.f32 %0, %1;" : "=r"(r) : "f"(x));
    return r;
}

__device__ __forceinline__ void mma_tf32(float c[4], const uint32_t a[4],
                                         const uint32_t b[2]) {
    asm volatile(
        "mma.sync.aligned.m16n8k8.row.col.f32.tf32.tf32.f32 "
        "{%0,%1,%2,%3}, {%4,%5,%6,%7}, {%8,%9}, {%0,%1,%2,%3};"
        : "+f"(c[0]), "+f"(c[1]), "+f"(c[2]), "+f"(c[3])
        : "r"(a[0]), "r"(a[1]), "r"(a[2]), "r"(a[3]), "r"(b[0]), "r"(b[1]));
}

// ---------------------------------------------------------------------------
__global__ void deg_kernel(const float* __restrict__ A) {
    int row  = blockIdx.x * (blockDim.x >> 5) + (threadIdx.x >> 5);
    int lane = threadIdx.x & 31;
    const float* r = A + (size_t)row * NN;
    float s = 0.f;
    for (int j = lane; j < NN; j += 32) s += r[j];
    #pragma unroll
    for (int o = 16; o; o >>= 1) s += __shfl_xor_sync(0xffffffffu, s, o);
    if (lane == 0) g_deg[row] = s;
}

__global__ void delta_kernel() {
    __shared__ float red[32];
    int tid = threadIdx.x;
    float s = 0.f;
    for (int i = tid; i < NN; i += blockDim.x) s += logf(g_deg[i] + 1.f);
    #pragma unroll
    for (int o = 16; o; o >>= 1) s += __shfl_xor_sync(0xffffffffu, s, o);
    if ((tid & 31) == 0) red[tid >> 5] = s;
    __syncthreads();
    if (tid < 32) {
        float v = (tid < (int)(blockDim.x >> 5)) ? red[tid] : 0.f;
        #pragma unroll
        for (int o = 16; o; o >>= 1) v += __shfl_xor_sync(0xffffffffu, v, o);
        if (tid == 0) g_delta = v / (float)NN;
    }
}

__global__ void transpose_kernel(const float* __restrict__ X) {
    int idx = blockIdx.x * blockDim.x + threadIdx.x;
    if (idx >= BB * PP * NN * CC) return;
    int ch = idx & (CC - 1);
    int j  = (idx >> 5) & (NN - 1);
    int bp = idx >> 16;
    int b = bp / PP, p = bp % PP;
    g_xp[idx] = X[(((size_t)b * CC + ch) * NN + j) * PP + p];
}

// ---------------------------------------------------------------------------
// Fused main kernel: tf32 mma.sync GEMM + aggregator epilogue + projection
// ---------------------------------------------------------------------------
__global__ __launch_bounds__(512, 1)
void pna_kernel(const float* __restrict__ A, const float* __restrict__ Theta,
                const float* __restrict__ Bias, float* __restrict__ out) {
    extern __shared__ float sm[];
    const int bp = blockIdx.y;
    const int i0 = blockIdx.x * TM;
    const int b  = bp / PP, p = bp % PP;
    const float* __restrict__ xp = g_xp + (size_t)bp * NN * CC;

    uint32_t* As = reinterpret_cast<uint32_t*>(sm);             // [TM][ASS] tf32 bits
    uint32_t* Fs = reinterpret_cast<uint32_t*>(sm) + TM * ASS;  // [KT][FSS] tf32 bits

    const int tid  = threadIdx.x;
    const int wid  = tid >> 5;
    const int lane = tid & 31;
    const int wm   = wid >> 2;          // warp row 0..3 (32 M each)
    const int wn   = wid & 3;           // warp col 0..3 (64 N each)
    const int lq   = lane >> 2;         // 0..7
    const int lr   = lane & 3;          // 0..3

    float acc[16][4];                   // [mt*8+nt][4]
    #pragma unroll
    for (int t = 0; t < 16; t++)
        #pragma unroll
        for (int j = 0; j < 4; j++) acc[t][j] = 0.f;

    // staging roles
    const int ati = tid >> 2;           // 0..127 dest row
    const int akk = (tid & 3) << 3;     // 0,8,16,24
    const int fkk = wid;                // 0..15 (F stage k row, +16 on it=1)
    const int fch = lane;

    // prefetch registers
    float4 pa0, pa1;
    float  px0, px1;
    {
        const float4* src = reinterpret_cast<const float4*>(
            A + (size_t)(i0 + ati) * NN + akk);
        pa0 = src[0]; pa1 = src[1];
        px0 = xp[(size_t)fkk * CC + fch];
        px1 = xp[(size_t)(16 + fkk) * CC + fch];
    }

    for (int k0 = 0; k0 < NN; k0 += KT) {
        // ---- stage A (tf32-rounded) ----
        {
            uint32_t* d = As + ati * ASS + akk;
            d[0] = rna_tf32(pa0.x); d[1] = rna_tf32(pa0.y);
            d[2] = rna_tf32(pa0.z); d[3] = rna_tf32(pa0.w);
            d[4] = rna_tf32(pa1.x); d[5] = rna_tf32(pa1.y);
            d[6] = rna_tf32(pa1.z); d[7] = rna_tf32(pa1.w);
        }
        // ---- stage F (8 features, tf32-rounded) ----
        #pragma unroll
        for (int it = 0; it < 2; it++) {
            float x = it ? px1 : px0;
            int kk = fkk + it * 16;
            float x2 = x * x;
            float ep = expf(x);
            float en = expf(-x);
            uint32_t* f = Fs + kk * FSS + fch;
            f[0]   = rna_tf32(x);
            f[32]  = rna_tf32(x2);
            f[64]  = rna_tf32(x2 * x);
            f[96]  = rna_tf32(x2 * x2);
            f[128] = rna_tf32(x * ep);
            f[160] = rna_tf32(ep);
            f[192] = rna_tf32(x * en);
            f[224] = rna_tf32(en);
        }
        __syncthreads();

        // ---- prefetch next stage ----
        if (k0 + KT < NN) {
            const float4* src = reinterpret_cast<const float4*>(
                A + (size_t)(i0 + ati) * NN + (k0 + KT) + akk);
            pa0 = src[0]; pa1 = src[1];
            px0 = xp[(size_t)(k0 + KT + fkk) * CC + fch];
            px1 = xp[(size_t)(k0 + KT + 16 + fkk) * CC + fch];
        }

        // ---- 128x256x32 via 4 k8-blocks of m16n8k8 ----
        #pragma unroll
        for (int kb = 0; kb < 4; kb++) {
            const int c0 = kb * 8 + lr;
            // A fragments (2 m-tiles)
            uint32_t af[2][4];
            #pragma unroll
            for (int mt = 0; mt < 2; mt++) {
                int r0 = (wm * 32 + mt * 16 + lq) * ASS;
                af[mt][0] = As[r0 + c0];
                af[mt][1] = As[r0 + 8 * ASS + c0];
                af[mt][2] = As[r0 + c0 + 4];
                af[mt][3] = As[r0 + 8 * ASS + c0 + 4];
            }
            // B fragments (8 n-tiles)
            uint32_t bf[8][2];
            const int n0 = wn * 64 + lq;
            #pragma unroll
            for (int nt = 0; nt < 8; nt++) {
                bf[nt][0] = Fs[c0 * FSS + n0 + nt * 8];
                bf[nt][1] = Fs[(c0 + 4) * FSS + n0 + nt * 8];
            }
            #pragma unroll
            for (int mt = 0; mt < 2; mt++)
                #pragma unroll
                for (int nt = 0; nt < 8; nt++)
                    mma_tf32(acc[mt * 8 + nt], af[mt], bf[nt]);
        }
        __syncthreads();
    }

    // ---- spill accumulators to smem ACC[128][ACCS] (overwrites As/Fs) ----
    float* ACC = sm;
    #pragma unroll
    for (int mt = 0; mt < 2; mt++) {
        int r = wm * 32 + mt * 16 + lq;
        #pragma unroll
        for (int nt = 0; nt < 8; nt++) {
            int c = wn * 64 + nt * 8 + lr * 2;
            float* a = acc[mt * 8 + nt];
            *reinterpret_cast<float2*>(&ACC[r * ACCS + c])       = make_float2(a[0], a[1]);
            *reinterpret_cast<float2*>(&ACC[(r + 8) * ACCS + c]) = make_float2(a[2], a[3]);
        }
    }
    __syncthreads();

    // ---- phase A: aggregator math, in place ----
    for (int e = tid; e < TM * CC; e += 512) {
        int i  = e >> 5;
        int ch = e & 31;
        float* row = &ACC[i * ACCS];
        float S1  = row[ch],       S2  = row[32 + ch];
        float S3  = row[64 + ch],  S4  = row[96 + ch];
        float SXP = row[128 + ch], SEP = row[160 + ch];
        float SXN = row[192 + ch], SEN = row[224 + ch];

        float x    = xp[(size_t)(i0 + i) * CC + ch];
        float dg   = g_deg[i0 + i];
        float dinv = 1.f / fmaxf(dg, EPSV);
        float m1 = S1 * dinv, m2 = S2 * dinv, m3 = S3 * dinv, m4 = S4 * dinv;
        float smax = SXP / (SEP + EPSV);
        float smin = SXN / (SEN + EPSV);
        float var  = fmaxf(m2 - m1 * m1, 0.f);
        float stdv = sqrtf(var + EPSV);
        float x2 = x * x, x3 = x2 * x, x4 = x2 * x2;
        float dist = x2 - 2.f * x * m1 + m2;
        float ed2  = x4 - 4.f * x3 * m1 + 6.f * x2 * m2 - 4.f * x * m3 + m4;
        float dstd = sqrtf(fmaxf(ed2 - dist * dist, 0.f) + EPSV);

        row[ch]        = smin;
        row[32  + ch]  = smax;
        row[64  + ch]  = m1;
        row[96  + ch]  = stdv;
        row[128 + ch]  = var;
        row[160 + ch]  = dist;
        row[192 + ch]  = dstd;
    }
    __syncthreads();

    // ---- phase B: scaler-folded Theta projection (f outer, 8 rows inner) ----
    const float delta = g_delta;
    const int ty = tid >> 5;   // 0..15, 8 rows each
    const int o  = lane;
    float s8[8], inv8[8], accO[8];
    #pragma unroll
    for (int r = 0; r < 8; r++) {
        int i = ty * 8 + r;
        float dg = g_deg[i0 + i];
        s8[r]   = logf(dg + 1.f) / delta;
        inv8[r] = 1.f / fmaxf(s8[r], EPSV);
        accO[r] = Bias[o];
    }
    #pragma unroll 4
    for (int f = 0; f < 224; f++) {
        float t0 = Theta[f * OUTC + o];
        float t1 = Theta[(224 + f) * OUTC + o];
        float t2 = Theta[(448 + f) * OUTC + o];
        #pragma unroll
        for (int r = 0; r < 8; r++) {
            float fv = ACC[(ty * 8 + r) * ACCS + f];
            float t  = fmaf(s8[r], t1, fmaf(inv8[r], t2, t0));
            accO[r]  = fmaf(fv, t, accO[r]);
        }
    }
    #pragma unroll
    for (int r = 0; r < 8; r++) {
        int i = ty * 8 + r;
        float v = accO[r];
        v = v > 0.f ? v : NEG_SLOPE * v;
        out[(((size_t)b * OUTC + o) * NN + (i0 + i)) * PP + p] = v;
    }
}

// ---------------------------------------------------------------------------
extern "C" void kernel_launch(void* const* d_in, const int* in_sizes, int n_in,
                              void* d_out, int out_size) {
    const float* X     = (const float*)d_in[0];   // [4,32,2048,12]
    const float* A     = (const float*)d_in[1];   // [2048,2048]
    const float* Theta = (const float*)d_in[2];   // [672,32]
    const float* Bias  = (const float*)d_in[3];   // [32]
    float* out = (float*)d_out;                   // [4,32,2048,12]

    cudaFuncSetAttribute(pna_kernel, cudaFuncAttributeMaxDynamicSharedMemorySize,
                         SMEM_BYTES);

    deg_kernel<<<NN / 8, 256>>>(A);
    delta_kernel<<<1, 1024>>>();
    transpose_kernel<<<(BB * PP * NN * CC + 255) / 256, 256>>>(X);

    dim3 grid(NN / TM, BB * PP);
    pna_kernel<<<grid, 512, SMEM_BYTES>>>(A, Theta, Bias, out);
}